// round 1
// baseline (speedup 1.0000x reference)
#include <cuda_runtime.h>
#include <math.h>

#define N_TOK 8192
#define DIM   1024
#define NE    8
#define NR    (N_TOK * 2)   // routed rows (top-2)

// ---------------- scratch (device globals; no allocation) ----------------
__device__ int   g_counts[NE];
__device__ int   g_offsets[NE];
__device__ int   g_cursor[NE];
__device__ int   g_tope[NR];
__device__ float g_topw[NR];
__device__ int   g_rows[NR];     // routed slot -> token index
__device__ float g_wts[NR];      // routed slot -> combine weight
__device__ float g_h[(size_t)NR * DIM];   // 67 MB hidden activations

// ---------------- init ----------------
__global__ void init_kernel() {
    int t = threadIdx.x;
    if (t < NE) { g_counts[t] = 0; g_cursor[t] = 0; }
}

// ---------------- gate: logits -> softmax -> top2 -> counts ----------------
__global__ void gate_kernel(const float* __restrict__ x,
                            const float* __restrict__ Wg,
                            const float* __restrict__ bg,
                            float* __restrict__ gate_out) {
    int warp = threadIdx.x >> 5;
    int lane = threadIdx.x & 31;
    int t = blockIdx.x * (blockDim.x >> 5) + warp;
    if (t >= N_TOK) return;

    const float* xr = x + (size_t)t * DIM;
    float acc[NE];
#pragma unroll
    for (int e = 0; e < NE; e++) acc[e] = 0.f;

#pragma unroll
    for (int i = 0; i < DIM / 128; i++) {          // 8 iterations
        int k0 = i * 128 + lane * 4;
        float4 xv = *(const float4*)(xr + k0);
        float xa[4] = {xv.x, xv.y, xv.z, xv.w};
#pragma unroll
        for (int c = 0; c < 4; c++) {
            const float4 w0 = *(const float4*)(Wg + (size_t)(k0 + c) * NE);
            const float4 w1 = *(const float4*)(Wg + (size_t)(k0 + c) * NE + 4);
            acc[0] += xa[c] * w0.x;  acc[1] += xa[c] * w0.y;
            acc[2] += xa[c] * w0.z;  acc[3] += xa[c] * w0.w;
            acc[4] += xa[c] * w1.x;  acc[5] += xa[c] * w1.y;
            acc[6] += xa[c] * w1.z;  acc[7] += xa[c] * w1.w;
        }
    }
#pragma unroll
    for (int e = 0; e < NE; e++)
#pragma unroll
        for (int o = 16; o > 0; o >>= 1)
            acc[e] += __shfl_xor_sync(0xffffffffu, acc[e], o);

    if (lane == 0) {
        float l[NE], p[NE];
        float m = -1e30f;
#pragma unroll
        for (int e = 0; e < NE; e++) { l[e] = acc[e] + bg[e]; m = fmaxf(m, l[e]); }
        float s = 0.f;
#pragma unroll
        for (int e = 0; e < NE; e++) { p[e] = expf(l[e] - m); s += p[e]; }
        float inv = 1.f / s;
#pragma unroll
        for (int e = 0; e < NE; e++) { p[e] *= inv; gate_out[(size_t)t * NE + e] = p[e]; }

        // top-2 (jax tie-break: first index wins, strict >)
        int e0 = 0; float p0 = p[0];
#pragma unroll
        for (int e = 1; e < NE; e++) if (p[e] > p0) { p0 = p[e]; e0 = e; }
        int e1 = -1; float p1 = -1e30f;
#pragma unroll
        for (int e = 0; e < NE; e++) if (e != e0 && p[e] > p1) { p1 = p[e]; e1 = e; }

        // softmax over [p0, p1] (renormalization per reference)
        float d  = p1 - p0;           // <= 0
        float ex = expf(d);
        float w0 = 1.f / (1.f + ex);
        float w1 = ex  / (1.f + ex);

        g_tope[2 * t + 0] = e0;  g_topw[2 * t + 0] = w0;
        g_tope[2 * t + 1] = e1;  g_topw[2 * t + 1] = w1;
        atomicAdd(&g_counts[e0], 1);
        atomicAdd(&g_counts[e1], 1);
    }
}

// ---------------- exclusive scan over 8 experts ----------------
__global__ void scan_kernel() {
    if (threadIdx.x == 0) {
        int s = 0;
        for (int e = 0; e < NE; e++) { g_offsets[e] = s; s += g_counts[e]; }
    }
}

// ---------------- compact routing lists ----------------
__global__ void route_kernel() {
    int i = blockIdx.x * blockDim.x + threadIdx.x;
    if (i >= NR) return;
    int e = g_tope[i];
    int pos  = atomicAdd(&g_cursor[e], 1);
    int slot = g_offsets[e] + pos;
    g_rows[slot] = i >> 1;
    g_wts[slot]  = g_topw[i];
}

// ---------------- expert GEMM: 128x128x16 tile, 8x8/thread ----------------
// LAYER==1: h = relu(gather(x) @ W1[e] + b1[e])        -> g_h
// LAYER==2: y[tok] += w * (h @ W2[e] + b2[e])          -> atomicAdd into out
template<int LAYER>
__global__ void expert_gemm(const float* __restrict__ Ax,
                            const float* __restrict__ W,
                            const float* __restrict__ bias,
                            float* __restrict__ out) {
    const int e = blockIdx.z;
    const int M = g_counts[e];
    const int row0 = blockIdx.y * 128;
    if (row0 >= M) return;
    const int base = g_offsets[e];
    const int bn0  = blockIdx.x * 128;
    const float* Wp = W + (size_t)e * DIM * DIM;
    const float* bp = bias + (size_t)e * DIM;

    __shared__ float As[16][128];
    __shared__ float Bs[16][132];   // row stride 132 floats (16B aligned)

    const int t  = threadIdx.x;     // 0..255
    const int tx = t & 15;          // col group
    const int ty = t >> 4;          // row group

    float acc[8][8];
#pragma unroll
    for (int i = 0; i < 8; i++)
#pragma unroll
        for (int j = 0; j < 8; j++) acc[i][j] = 0.f;

    for (int k0 = 0; k0 < DIM; k0 += 16) {
        // load A tile (gathered for layer 1)
#pragma unroll
        for (int u = 0; u < 2; u++) {
            int idx = t + u * 256;          // 0..511
            int r   = idx >> 2;             // 0..127
            int c4  = (idx & 3) * 4;        // 0,4,8,12
            int rL  = row0 + r;
            float4 v = make_float4(0.f, 0.f, 0.f, 0.f);
            if (rL < M) {
                const float* ap;
                if (LAYER == 1) {
                    int tok = g_rows[base + rL];
                    ap = Ax + (size_t)tok * DIM;
                } else {
                    ap = g_h + (size_t)(base + rL) * DIM;
                }
                v = *(const float4*)(ap + k0 + c4);
            }
            As[c4 + 0][r] = v.x; As[c4 + 1][r] = v.y;
            As[c4 + 2][r] = v.z; As[c4 + 3][r] = v.w;
        }
        // load B tile (coalesced along N)
#pragma unroll
        for (int u = 0; u < 2; u++) {
            int idx = t + u * 256;
            int kk  = idx >> 5;             // 0..15
            int c4  = (idx & 31) * 4;       // 0..124
            float4 v = *(const float4*)(Wp + (size_t)(k0 + kk) * DIM + bn0 + c4);
            *(float4*)(&Bs[kk][c4]) = v;
        }
        __syncthreads();

#pragma unroll
        for (int k = 0; k < 16; k++) {
            float ra[8], rb[8];
            float4 a0 = *(const float4*)(&As[k][ty * 8]);
            float4 a1 = *(const float4*)(&As[k][ty * 8 + 4]);
            ra[0]=a0.x; ra[1]=a0.y; ra[2]=a0.z; ra[3]=a0.w;
            ra[4]=a1.x; ra[5]=a1.y; ra[6]=a1.z; ra[7]=a1.w;
            // split-N micro-tile: cols tx*4..+3 and 64+tx*4..+3 (conflict-free)
            float4 b0 = *(const float4*)(&Bs[k][tx * 4]);
            float4 b1v = *(const float4*)(&Bs[k][64 + tx * 4]);
            rb[0]=b0.x; rb[1]=b0.y; rb[2]=b0.z; rb[3]=b0.w;
            rb[4]=b1v.x; rb[5]=b1v.y; rb[6]=b1v.z; rb[7]=b1v.w;
#pragma unroll
            for (int i = 0; i < 8; i++)
#pragma unroll
                for (int j = 0; j < 8; j++)
                    acc[i][j] += ra[i] * rb[j];
        }
        __syncthreads();
    }

    // epilogue
#pragma unroll
    for (int i = 0; i < 8; i++) {
        int rL = row0 + ty * 8 + i;
        if (rL >= M) continue;
        int gslot = base + rL;
        if (LAYER == 1) {
#pragma unroll
            for (int half = 0; half < 2; half++) {
                int c = bn0 + half * 64 + tx * 4;
                float4 bb = *(const float4*)(bp + c);
                float4 v;
                v.x = fmaxf(acc[i][half*4+0] + bb.x, 0.f);
                v.y = fmaxf(acc[i][half*4+1] + bb.y, 0.f);
                v.z = fmaxf(acc[i][half*4+2] + bb.z, 0.f);
                v.w = fmaxf(acc[i][half*4+3] + bb.w, 0.f);
                *(float4*)(g_h + (size_t)gslot * DIM + c) = v;
            }
        } else {
            int tok = g_rows[gslot];
            float w = g_wts[gslot];
            float* yr = out + (size_t)tok * DIM;
#pragma unroll
            for (int half = 0; half < 2; half++) {
                int c = bn0 + half * 64 + tx * 4;
                float4 bb = *(const float4*)(bp + c);
                atomicAdd(yr + c + 0, w * (acc[i][half*4+0] + bb.x));
                atomicAdd(yr + c + 1, w * (acc[i][half*4+1] + bb.y));
                atomicAdd(yr + c + 2, w * (acc[i][half*4+2] + bb.z));
                atomicAdd(yr + c + 3, w * (acc[i][half*4+3] + bb.w));
            }
        }
    }
}

// ---------------- launch ----------------
extern "C" void kernel_launch(void* const* d_in, const int* in_sizes, int n_in,
                              void* d_out, int out_size) {
    const float* x  = (const float*)d_in[0];
    const float* Wg = (const float*)d_in[1];
    const float* bg = (const float*)d_in[2];
    const float* W1 = (const float*)d_in[3];
    const float* b1 = (const float*)d_in[4];
    const float* W2 = (const float*)d_in[5];
    const float* b2 = (const float*)d_in[6];

    float* y        = (float*)d_out;
    float* gate_out = (float*)d_out + (size_t)N_TOK * DIM;   // concat(y, gate_prob)

    // zero y (poisoned by harness); gate_prob fully overwritten by gate_kernel
    cudaMemsetAsync(d_out, 0, (size_t)N_TOK * DIM * sizeof(float), 0);

    init_kernel<<<1, 32>>>();
    gate_kernel<<<N_TOK / 8, 256>>>(x, Wg, bg, gate_out);
    scan_kernel<<<1, 1>>>();
    route_kernel<<<NR / 256, 256>>>();

    dim3 grid(DIM / 128, N_TOK / 128, NE);   // (col tiles, worst-case row tiles, experts)
    expert_gemm<1><<<grid, 256>>>(x,   W1, b1, nullptr);
    expert_gemm<2><<<grid, 256>>>(nullptr, W2, b2, y);
}

// round 2
// speedup vs baseline: 1.2648x; 1.2648x over previous
#include <cuda_runtime.h>
#include <math.h>

#define N_TOK 8192
#define DIM   1024
#define NE    8
#define NR    (N_TOK * 2)   // routed rows (top-2)

typedef unsigned long long u64;

// ---------------- scratch (device globals; no allocation) ----------------
__device__ int   g_counts[NE];
__device__ int   g_offsets[NE];
__device__ int   g_cursor[NE];
__device__ int   g_tope[NR];
__device__ float g_topw[NR];
__device__ int   g_rows[NR];     // routed slot -> token index
__device__ float g_wts[NR];      // routed slot -> combine weight
__device__ float g_h[(size_t)NR * DIM];   // 67 MB hidden activations

// ---------------- packed f32x2 helpers ----------------
__device__ __forceinline__ u64 pack2(float lo, float hi) {
    u64 r; asm("mov.b64 %0, {%1, %2};" : "=l"(r) : "f"(lo), "f"(hi)); return r;
}
__device__ __forceinline__ void unpack2(u64 v, float& lo, float& hi) {
    asm("mov.b64 {%0, %1}, %2;" : "=f"(lo), "=f"(hi) : "l"(v));
}
__device__ __forceinline__ void ffma2(u64& d, u64 a, u64 b) {
    asm("fma.rn.f32x2 %0, %1, %2, %0;" : "+l"(d) : "l"(a), "l"(b));
}

// ---------------- init ----------------
__global__ void init_kernel() {
    int t = threadIdx.x;
    if (t < NE) { g_counts[t] = 0; g_cursor[t] = 0; }
}

// ---------------- gate: logits -> softmax -> top2 -> counts ----------------
__global__ void gate_kernel(const float* __restrict__ x,
                            const float* __restrict__ Wg,
                            const float* __restrict__ bg,
                            float* __restrict__ gate_out) {
    int warp = threadIdx.x >> 5;
    int lane = threadIdx.x & 31;
    int t = blockIdx.x * (blockDim.x >> 5) + warp;
    if (t >= N_TOK) return;

    const float* xr = x + (size_t)t * DIM;
    float acc[NE];
#pragma unroll
    for (int e = 0; e < NE; e++) acc[e] = 0.f;

#pragma unroll
    for (int i = 0; i < DIM / 128; i++) {          // 8 iterations
        int k0 = i * 128 + lane * 4;
        float4 xv = *(const float4*)(xr + k0);
        float xa[4] = {xv.x, xv.y, xv.z, xv.w};
#pragma unroll
        for (int c = 0; c < 4; c++) {
            const float4 w0 = *(const float4*)(Wg + (size_t)(k0 + c) * NE);
            const float4 w1 = *(const float4*)(Wg + (size_t)(k0 + c) * NE + 4);
            acc[0] += xa[c] * w0.x;  acc[1] += xa[c] * w0.y;
            acc[2] += xa[c] * w0.z;  acc[3] += xa[c] * w0.w;
            acc[4] += xa[c] * w1.x;  acc[5] += xa[c] * w1.y;
            acc[6] += xa[c] * w1.z;  acc[7] += xa[c] * w1.w;
        }
    }
#pragma unroll
    for (int e = 0; e < NE; e++)
#pragma unroll
        for (int o = 16; o > 0; o >>= 1)
            acc[e] += __shfl_xor_sync(0xffffffffu, acc[e], o);

    if (lane == 0) {
        float l[NE], p[NE];
        float m = -1e30f;
#pragma unroll
        for (int e = 0; e < NE; e++) { l[e] = acc[e] + bg[e]; m = fmaxf(m, l[e]); }
        float s = 0.f;
#pragma unroll
        for (int e = 0; e < NE; e++) { p[e] = expf(l[e] - m); s += p[e]; }
        float inv = 1.f / s;
#pragma unroll
        for (int e = 0; e < NE; e++) { p[e] *= inv; gate_out[(size_t)t * NE + e] = p[e]; }

        // top-2 (jax tie-break: first index wins, strict >)
        int e0 = 0; float p0 = p[0];
#pragma unroll
        for (int e = 1; e < NE; e++) if (p[e] > p0) { p0 = p[e]; e0 = e; }
        int e1 = -1; float p1 = -1e30f;
#pragma unroll
        for (int e = 0; e < NE; e++) if (e != e0 && p[e] > p1) { p1 = p[e]; e1 = e; }

        // softmax over [p0, p1] (renormalization per reference)
        float d  = p1 - p0;           // <= 0
        float ex = expf(d);
        float w0 = 1.f / (1.f + ex);
        float w1 = ex  / (1.f + ex);

        g_tope[2 * t + 0] = e0;  g_topw[2 * t + 0] = w0;
        g_tope[2 * t + 1] = e1;  g_topw[2 * t + 1] = w1;
        atomicAdd(&g_counts[e0], 1);
        atomicAdd(&g_counts[e1], 1);
    }
}

// ---------------- exclusive scan over 8 experts ----------------
__global__ void scan_kernel() {
    if (threadIdx.x == 0) {
        int s = 0;
        for (int e = 0; e < NE; e++) { g_offsets[e] = s; s += g_counts[e]; }
    }
}

// ---------------- compact routing lists ----------------
__global__ void route_kernel() {
    int i = blockIdx.x * blockDim.x + threadIdx.x;
    if (i >= NR) return;
    int e = g_tope[i];
    int pos  = atomicAdd(&g_cursor[e], 1);
    int slot = g_offsets[e] + pos;
    g_rows[slot] = i >> 1;
    g_wts[slot]  = g_topw[i];
}

// ---------------- expert GEMM: 128x128x16 tile, 8x8/thread, f32x2 math ----
// LAYER==1: h = relu(gather(x) @ W1[e] + b1[e])        -> g_h
// LAYER==2: y[tok] += w * (h @ W2[e] + b2[e])          -> atomicAdd into out
template<int LAYER>
__global__ void __launch_bounds__(256, 2) expert_gemm(
                            const float* __restrict__ Ax,
                            const float* __restrict__ W,
                            const float* __restrict__ bias,
                            float* __restrict__ out) {
    const int e = blockIdx.z;
    const int M = g_counts[e];
    const int row0 = blockIdx.y * 128;
    if (row0 >= M) return;
    const int base = g_offsets[e];
    const int bn0  = blockIdx.x * 128;
    const float* Wp = W + (size_t)e * DIM * DIM;
    const float* bp = bias + (size_t)e * DIM;

    __shared__ float As[16][128];
    __shared__ float Bs[16][132];   // row stride 132 floats (= 33*16B, keeps 16B align)

    const int t  = threadIdx.x;     // 0..255
    const int tx = t & 15;          // col group
    const int ty = t >> 4;          // row group

    // packed accumulators: accp[i][j] covers output cols pair j (see epilogue)
    u64 accp[8][4];
#pragma unroll
    for (int i = 0; i < 8; i++)
#pragma unroll
        for (int j = 0; j < 4; j++) accp[i][j] = 0ull;

    for (int k0 = 0; k0 < DIM; k0 += 16) {
        // load A tile (gathered for layer 1)
#pragma unroll
        for (int u = 0; u < 2; u++) {
            int idx = t + u * 256;          // 0..511
            int r   = idx >> 2;             // 0..127
            int c4  = (idx & 3) * 4;        // 0,4,8,12
            int rL  = row0 + r;
            float4 v = make_float4(0.f, 0.f, 0.f, 0.f);
            if (rL < M) {
                const float* ap;
                if (LAYER == 1) {
                    int tok = g_rows[base + rL];
                    ap = Ax + (size_t)tok * DIM;
                } else {
                    ap = g_h + (size_t)(base + rL) * DIM;
                }
                v = *(const float4*)(ap + k0 + c4);
            }
            As[c4 + 0][r] = v.x; As[c4 + 1][r] = v.y;
            As[c4 + 2][r] = v.z; As[c4 + 3][r] = v.w;
        }
        // load B tile (coalesced along N)
#pragma unroll
        for (int u = 0; u < 2; u++) {
            int idx = t + u * 256;
            int kk  = idx >> 5;             // 0..15
            int c4  = (idx & 31) * 4;       // 0..124
            float4 v = *(const float4*)(Wp + (size_t)(k0 + kk) * DIM + bn0 + c4);
            *(float4*)(&Bs[kk][c4]) = v;
        }
        __syncthreads();

#pragma unroll
        for (int k = 0; k < 16; k++) {
            // A fragment: broadcast each scalar into both f32x2 lanes
            float4 a0 = *(const float4*)(&As[k][ty * 8]);
            float4 a1 = *(const float4*)(&As[k][ty * 8 + 4]);
            u64 ap2[8];
            ap2[0] = pack2(a0.x, a0.x); ap2[1] = pack2(a0.y, a0.y);
            ap2[2] = pack2(a0.z, a0.z); ap2[3] = pack2(a0.w, a0.w);
            ap2[4] = pack2(a1.x, a1.x); ap2[5] = pack2(a1.y, a1.y);
            ap2[6] = pack2(a1.z, a1.z); ap2[7] = pack2(a1.w, a1.w);
            // B fragment: consecutive floats reinterpret directly as f32x2 pairs
            // (Bs row base + tx*4 floats is 16B-aligned: 132*4=528=33*16)
            const u64* b64a = (const u64*)(&Bs[k][tx * 4]);
            const u64* b64b = (const u64*)(&Bs[k][64 + tx * 4]);
            u64 rbp[4];
            rbp[0] = b64a[0]; rbp[1] = b64a[1];
            rbp[2] = b64b[0]; rbp[3] = b64b[1];
#pragma unroll
            for (int i = 0; i < 8; i++) {
                ffma2(accp[i][0], ap2[i], rbp[0]);
                ffma2(accp[i][1], ap2[i], rbp[1]);
                ffma2(accp[i][2], ap2[i], rbp[2]);
                ffma2(accp[i][3], ap2[i], rbp[3]);
            }
        }
        __syncthreads();
    }

    // epilogue: pair j=0 -> cols tx*4+{0,1}, j=1 -> tx*4+{2,3},
    //           j=2 -> 64+tx*4+{0,1}, j=3 -> 64+tx*4+{2,3}
#pragma unroll
    for (int i = 0; i < 8; i++) {
        int rL = row0 + ty * 8 + i;
        if (rL >= M) continue;
        int gslot = base + rL;
        float a[8];
        unpack2(accp[i][0], a[0], a[1]);
        unpack2(accp[i][1], a[2], a[3]);
        unpack2(accp[i][2], a[4], a[5]);
        unpack2(accp[i][3], a[6], a[7]);
        if (LAYER == 1) {
#pragma unroll
            for (int half = 0; half < 2; half++) {
                int c = bn0 + half * 64 + tx * 4;
                float4 bb = *(const float4*)(bp + c);
                float4 v;
                v.x = fmaxf(a[half*4+0] + bb.x, 0.f);
                v.y = fmaxf(a[half*4+1] + bb.y, 0.f);
                v.z = fmaxf(a[half*4+2] + bb.z, 0.f);
                v.w = fmaxf(a[half*4+3] + bb.w, 0.f);
                *(float4*)(g_h + (size_t)gslot * DIM + c) = v;
            }
        } else {
            int tok = g_rows[gslot];
            float w = g_wts[gslot];
            float* yr = out + (size_t)tok * DIM;
#pragma unroll
            for (int half = 0; half < 2; half++) {
                int c = bn0 + half * 64 + tx * 4;
                float4 bb = *(const float4*)(bp + c);
                atomicAdd(yr + c + 0, w * (a[half*4+0] + bb.x));
                atomicAdd(yr + c + 1, w * (a[half*4+1] + bb.y));
                atomicAdd(yr + c + 2, w * (a[half*4+2] + bb.z));
                atomicAdd(yr + c + 3, w * (a[half*4+3] + bb.w));
            }
        }
    }
}

// ---------------- launch ----------------
extern "C" void kernel_launch(void* const* d_in, const int* in_sizes, int n_in,
                              void* d_out, int out_size) {
    const float* x  = (const float*)d_in[0];
    const float* Wg = (const float*)d_in[1];
    const float* bg = (const float*)d_in[2];
    const float* W1 = (const float*)d_in[3];
    const float* b1 = (const float*)d_in[4];
    const float* W2 = (const float*)d_in[5];
    const float* b2 = (const float*)d_in[6];

    float* y        = (float*)d_out;
    float* gate_out = (float*)d_out + (size_t)N_TOK * DIM;   // concat(y, gate_prob)

    // zero y (poisoned by harness); gate_prob fully overwritten by gate_kernel
    cudaMemsetAsync(d_out, 0, (size_t)N_TOK * DIM * sizeof(float), 0);

    init_kernel<<<1, 32>>>();
    gate_kernel<<<N_TOK / 8, 256>>>(x, Wg, bg, gate_out);
    scan_kernel<<<1, 1>>>();
    route_kernel<<<NR / 256, 256>>>();

    dim3 grid(DIM / 128, N_TOK / 128, NE);   // (col tiles, worst-case row tiles, experts)
    expert_gemm<1><<<grid, 256>>>(x,   W1, b1, nullptr);
    expert_gemm<2><<<grid, 256>>>(nullptr, W2, b2, y);
}

// round 5
// speedup vs baseline: 1.8994x; 1.5018x over previous
#include <cuda_runtime.h>
#include <cuda_fp16.h>
#include <math.h>
#include <stdint.h>

#define N_TOK 8192
#define DIM   1024
#define NE    8
#define NR    (N_TOK * 2)

typedef uint32_t u32;

// ---------------- scratch (device globals; no allocation) ----------------
__device__ int   g_counts[NE];
__device__ int   g_offsets[NE];
__device__ int   g_cursor[NE];
__device__ int   g_tope[NR];
__device__ float g_topw[NR];
__device__ int   g_rows[NR + 128];
__device__ float g_wts[NR + 128];
__device__ float g_h[(size_t)(NR + 128) * DIM];       // hidden activations (padded)
__device__ __half g_wt_hi[2][NE][DIM][DIM];           // W^T [n][k], fp16 hi
__device__ __half g_wt_lo[2][NE][DIM][DIM];           // fp16 lo (residual)

// ---------------- init ----------------
__global__ void init_kernel() {
    int t = threadIdx.x;
    if (t < NE) { g_counts[t] = 0; g_cursor[t] = 0; }
}

// ---------------- gate ----------------
__global__ void gate_kernel(const float* __restrict__ x,
                            const float* __restrict__ Wg,
                            const float* __restrict__ bg,
                            float* __restrict__ gate_out) {
    int warp = threadIdx.x >> 5;
    int lane = threadIdx.x & 31;
    int t = blockIdx.x * (blockDim.x >> 5) + warp;
    if (t >= N_TOK) return;

    const float* xr = x + (size_t)t * DIM;
    float acc[NE];
#pragma unroll
    for (int e = 0; e < NE; e++) acc[e] = 0.f;
#pragma unroll
    for (int i = 0; i < DIM / 128; i++) {
        int k0 = i * 128 + lane * 4;
        float4 xv = *(const float4*)(xr + k0);
        float xa[4] = {xv.x, xv.y, xv.z, xv.w};
#pragma unroll
        for (int c = 0; c < 4; c++) {
            const float4 w0 = *(const float4*)(Wg + (size_t)(k0 + c) * NE);
            const float4 w1 = *(const float4*)(Wg + (size_t)(k0 + c) * NE + 4);
            acc[0] += xa[c] * w0.x;  acc[1] += xa[c] * w0.y;
            acc[2] += xa[c] * w0.z;  acc[3] += xa[c] * w0.w;
            acc[4] += xa[c] * w1.x;  acc[5] += xa[c] * w1.y;
            acc[6] += xa[c] * w1.z;  acc[7] += xa[c] * w1.w;
        }
    }
#pragma unroll
    for (int e = 0; e < NE; e++)
#pragma unroll
        for (int o = 16; o > 0; o >>= 1)
            acc[e] += __shfl_xor_sync(0xffffffffu, acc[e], o);

    if (lane == 0) {
        float l[NE], p[NE];
        float m = -1e30f;
#pragma unroll
        for (int e = 0; e < NE; e++) { l[e] = acc[e] + bg[e]; m = fmaxf(m, l[e]); }
        float s = 0.f;
#pragma unroll
        for (int e = 0; e < NE; e++) { p[e] = expf(l[e] - m); s += p[e]; }
        float inv = 1.f / s;
#pragma unroll
        for (int e = 0; e < NE; e++) { p[e] *= inv; gate_out[(size_t)t * NE + e] = p[e]; }

        int e0 = 0; float p0 = p[0];
#pragma unroll
        for (int e = 1; e < NE; e++) if (p[e] > p0) { p0 = p[e]; e0 = e; }
        int e1 = -1; float p1 = -1e30f;
#pragma unroll
        for (int e = 0; e < NE; e++) if (e != e0 && p[e] > p1) { p1 = p[e]; e1 = e; }

        float d  = p1 - p0;
        float ex = expf(d);
        float w0 = 1.f / (1.f + ex);
        float w1 = ex  / (1.f + ex);

        g_tope[2 * t + 0] = e0;  g_topw[2 * t + 0] = w0;
        g_tope[2 * t + 1] = e1;  g_topw[2 * t + 1] = w1;
        atomicAdd(&g_counts[e0], 1);
        atomicAdd(&g_counts[e1], 1);
    }
}

__global__ void scan_kernel() {
    if (threadIdx.x == 0) {
        int s = 0;
        for (int e = 0; e < NE; e++) { g_offsets[e] = s; s += g_counts[e]; }
    }
}

__global__ void route_kernel() {
    int i = blockIdx.x * blockDim.x + threadIdx.x;
    if (i >= NR) return;
    int e = g_tope[i];
    int pos  = atomicAdd(&g_cursor[e], 1);
    int slot = g_offsets[e] + pos;
    g_rows[slot] = i >> 1;
    g_wts[slot]  = g_topw[i];
}

// ---------------- W transpose + fp16 hi/lo split ----------------
__global__ void convert_w_kernel(const float* __restrict__ W1,
                                 const float* __restrict__ W2) {
    __shared__ float t[32][33];
    int z = blockIdx.z;               // layer*8 + e
    int layer = z >> 3, e = z & 7;
    int k0 = blockIdx.x * 32, n0 = blockIdx.y * 32;
    int tx = threadIdx.x & 31, ty = threadIdx.x >> 5;

    const float* src = (layer ? W2 : W1) + (size_t)e * DIM * DIM;
#pragma unroll
    for (int i = 0; i < 4; i++) {
        int kk = ty + i * 8;
        t[kk][tx] = src[(size_t)(k0 + kk) * DIM + n0 + tx];
    }
    __syncthreads();
#pragma unroll
    for (int i = 0; i < 4; i++) {
        int nn = ty + i * 8;
        float f = t[tx][nn];
        __half h = __float2half_rn(f);
        __half l = __float2half_rn(f - __half2float(h));
        size_t idx = (size_t)(n0 + nn) * DIM + k0 + tx;
        g_wt_hi[layer][e][0][idx] = h;
        g_wt_lo[layer][e][0][idx] = l;
    }
}

// ---------------- HMMA mma.sync GEMM, fp16 3-split -----------------------
// CTA 128x128, BK=32, 8 warps (4 M x 2 N), warp tile 32x64, m16n8k16.
#define BK     32
#define SRD    40                     // smem row stride in halfs (conflict-free)
#define TILE_H (128 * SRD)            // 5120 halfs per matrix
#define AHI_O  0
#define ALO_O  TILE_H
#define BHI_O  (2 * TILE_H)
#define BLO_O  (3 * TILE_H)
#define STG_H  (4 * TILE_H)           // 20480 halfs = 40KB per stage
#define SMEM_B (2 * STG_H * 2)        // 80KB

#define MMA16816(d, a0, a1, a2, a3, b0, b1) \
    asm volatile("mma.sync.aligned.m16n8k16.row.col.f32.f16.f16.f32 " \
        "{%0,%1,%2,%3}, {%4,%5,%6,%7}, {%8,%9}, {%0,%1,%2,%3};" \
        : "+f"((d)[0]), "+f"((d)[1]), "+f"((d)[2]), "+f"((d)[3]) \
        : "r"(a0), "r"(a1), "r"(a2), "r"(a3), "r"(b0), "r"(b1))

template<int LAYER>
__global__ void __launch_bounds__(256, 1) moe_hmma_kernel(
        const float* __restrict__ Ax,
        const float* __restrict__ bias,
        float* __restrict__ out) {
    const int e = blockIdx.z;
    const int M = g_counts[e];
    const int row0 = blockIdx.y * 128;
    if (row0 >= M) return;
    const int base = g_offsets[e];
    const int bn0  = blockIdx.x * 128;
    const float* bp = bias + (size_t)e * DIM;   // FIX: per-expert bias offset

    extern __shared__ __half sh[];

    const int tid = threadIdx.x;
    const int wid = tid >> 5, lane = tid & 31;
    const int wm = wid >> 1, wn = wid & 1;
    const int g = lane >> 2, q = lane & 3;

    // ---- loader role: thread t handles row r, k-halfword half hsel ----
    const int r    = tid >> 1;
    const int ks   = (tid & 1) * 16;
    const int rL   = row0 + r;
    const bool av  = (rL < M);
    const int rr   = av ? rL : 0;
    const float* arow;
    if (LAYER == 1) arow = Ax + (size_t)g_rows[base + rr] * DIM;
    else            arow = g_h + (size_t)(base + rr) * DIM;
    const float4* a4 = (const float4*)arow;
    const __half* bh_row = &g_wt_hi[LAYER - 1][e][bn0 + r][0];
    const __half* bl_row = &g_wt_lo[LAYER - 1][e][bn0 + r][0];

    float acc[16][4];
#pragma unroll
    for (int i = 0; i < 16; i++)
#pragma unroll
        for (int j = 0; j < 4; j++) acc[i][j] = 0.f;

    float4 fa[4];
    uint4  vbh[2], vbl[2];

    // global loads for stage c into regs
    auto LOADG = [&](int c) {
        int k0 = c * BK + ks;
        if (av) {
#pragma unroll
            for (int i = 0; i < 4; i++) fa[i] = a4[k0 / 4 + i];
        } else {
#pragma unroll
            for (int i = 0; i < 4; i++) fa[i] = make_float4(0.f, 0.f, 0.f, 0.f);
        }
#pragma unroll
        for (int i = 0; i < 2; i++) {
            vbh[i] = *(const uint4*)(bh_row + k0 + i * 8);
            vbl[i] = *(const uint4*)(bl_row + k0 + i * 8);
        }
    };
    // convert + store regs into smem stage s
    auto STORE = [&](int s) {
        __half* p = sh + s * STG_H;
        float fs[16] = {fa[0].x, fa[0].y, fa[0].z, fa[0].w,
                        fa[1].x, fa[1].y, fa[1].z, fa[1].w,
                        fa[2].x, fa[2].y, fa[2].z, fa[2].w,
                        fa[3].x, fa[3].y, fa[3].z, fa[3].w};
        uint4 hv[2], lv[2];
        __half* hp = (__half*)hv;
        __half* lp = (__half*)lv;
#pragma unroll
        for (int j = 0; j < 16; j++) {
            __half hh = __float2half_rn(fs[j]);
            hp[j] = hh;
            lp[j] = __float2half_rn(fs[j] - __half2float(hh));
        }
        int o = r * SRD + ks;
        *(uint4*)(p + AHI_O + o)     = hv[0];
        *(uint4*)(p + AHI_O + o + 8) = hv[1];
        *(uint4*)(p + ALO_O + o)     = lv[0];
        *(uint4*)(p + ALO_O + o + 8) = lv[1];
        *(uint4*)(p + BHI_O + o)     = vbh[0];
        *(uint4*)(p + BHI_O + o + 8) = vbh[1];
        *(uint4*)(p + BLO_O + o)     = vbl[0];
        *(uint4*)(p + BLO_O + o + 8) = vbl[1];
    };

    LOADG(0);
    STORE(0);

    const int NSTG = DIM / BK;   // 32
    for (int c = 0; c < NSTG; c++) {
        __syncthreads();
        const bool more = (c + 1 < NSTG);
        if (more) LOADG(c + 1);

        const __half* p = sh + (c & 1) * STG_H;
#pragma unroll
        for (int k16 = 0; k16 < 2; k16++) {
            u32 af[2][2][4];
#pragma unroll
            for (int ms = 0; ms < 2; ms++) {
                int ab = (wm * 32 + ms * 16 + g) * SRD + k16 * 16 + q * 2;
#pragma unroll
                for (int sp = 0; sp < 2; sp++) {
                    const __half* ap = p + (sp ? ALO_O : AHI_O) + ab;
                    af[ms][sp][0] = *(const u32*)(ap);
                    af[ms][sp][1] = *(const u32*)(ap + 8 * SRD);
                    af[ms][sp][2] = *(const u32*)(ap + 8);
                    af[ms][sp][3] = *(const u32*)(ap + 8 * SRD + 8);
                }
            }
#pragma unroll
            for (int nt = 0; nt < 8; nt++) {
                int bb = (wn * 64 + nt * 8 + g) * SRD + k16 * 16 + q * 2;
                u32 bh0 = *(const u32*)(p + BHI_O + bb);
                u32 bh1 = *(const u32*)(p + BHI_O + bb + 8);
                u32 bl0 = *(const u32*)(p + BLO_O + bb);
                u32 bl1 = *(const u32*)(p + BLO_O + bb + 8);
#pragma unroll
                for (int ms = 0; ms < 2; ms++) {
                    float* d = acc[ms * 8 + nt];
                    MMA16816(d, af[ms][0][0], af[ms][0][1], af[ms][0][2], af[ms][0][3], bh0, bh1);
                    MMA16816(d, af[ms][0][0], af[ms][0][1], af[ms][0][2], af[ms][0][3], bl0, bl1);
                    MMA16816(d, af[ms][1][0], af[ms][1][1], af[ms][1][2], af[ms][1][3], bh0, bh1);
                }
            }
        }
        if (more) STORE((c + 1) & 1);
    }

    // ---- epilogue: acc[ms*8+nt][{c0,c1,c2,c3}] ----
#pragma unroll
    for (int ms = 0; ms < 2; ms++) {
#pragma unroll
        for (int half = 0; half < 2; half++) {    // c0c1 row / c2c3 row (+8)
            int rloc = row0 + wm * 32 + ms * 16 + g + half * 8;
            if (rloc >= M) continue;
            int gslot = base + rloc;
            if (LAYER == 1) {
                float* hrow = g_h + (size_t)gslot * DIM;
#pragma unroll
                for (int nt = 0; nt < 8; nt++) {
                    int col = bn0 + wn * 64 + nt * 8 + q * 2;
                    float b0 = bp[col], b1 = bp[col + 1];
                    float v0 = fmaxf(acc[ms * 8 + nt][half * 2 + 0] + b0, 0.f);
                    float v1 = fmaxf(acc[ms * 8 + nt][half * 2 + 1] + b1, 0.f);
                    *(float2*)(hrow + col) = make_float2(v0, v1);
                }
            } else {
                int tok = g_rows[gslot];
                float cw = g_wts[gslot];
                float* yr = out + (size_t)tok * DIM;
#pragma unroll
                for (int nt = 0; nt < 8; nt++) {
                    int col = bn0 + wn * 64 + nt * 8 + q * 2;
                    float b0 = bp[col], b1 = bp[col + 1];
                    atomicAdd(yr + col + 0, cw * (acc[ms * 8 + nt][half * 2 + 0] + b0));
                    atomicAdd(yr + col + 1, cw * (acc[ms * 8 + nt][half * 2 + 1] + b1));
                }
            }
        }
    }
}

// ---------------- launch ----------------
extern "C" void kernel_launch(void* const* d_in, const int* in_sizes, int n_in,
                              void* d_out, int out_size) {
    const float* x  = (const float*)d_in[0];
    const float* Wg = (const float*)d_in[1];
    const float* bg = (const float*)d_in[2];
    const float* W1 = (const float*)d_in[3];
    const float* b1 = (const float*)d_in[4];
    const float* W2 = (const float*)d_in[5];
    const float* b2 = (const float*)d_in[6];

    float* y        = (float*)d_out;
    float* gate_out = (float*)d_out + (size_t)N_TOK * DIM;

    static int attr_done = 0;
    if (!attr_done) {
        cudaFuncSetAttribute(moe_hmma_kernel<1>,
            cudaFuncAttributeMaxDynamicSharedMemorySize, SMEM_B);
        cudaFuncSetAttribute(moe_hmma_kernel<2>,
            cudaFuncAttributeMaxDynamicSharedMemorySize, SMEM_B);
        attr_done = 1;
    }

    cudaMemsetAsync(d_out, 0, (size_t)N_TOK * DIM * sizeof(float), 0);

    init_kernel<<<1, 32>>>();
    convert_w_kernel<<<dim3(DIM / 32, DIM / 32, 16), 256>>>(W1, W2);
    gate_kernel<<<N_TOK / 8, 256>>>(x, Wg, bg, gate_out);
    scan_kernel<<<1, 1>>>();
    route_kernel<<<NR / 256, 256>>>();

    dim3 grid(DIM / 128, NR / 128, NE);
    moe_hmma_kernel<1><<<grid, 256, SMEM_B>>>(x, b1, nullptr);
    moe_hmma_kernel<2><<<grid, 256, SMEM_B>>>(nullptr, b2, y);
}

// round 6
// speedup vs baseline: 2.4021x; 1.2646x over previous
#include <cuda_runtime.h>
#include <cuda_fp16.h>
#include <math.h>
#include <stdint.h>

#define N_TOK 8192
#define DIM   1024
#define NE    8
#define NR    (N_TOK * 2)

typedef uint32_t u32;

// ---------------- scratch (device globals; no allocation) ----------------
__device__ int   g_counts[NE];
__device__ int   g_offsets[NE];
__device__ int   g_cursor[NE];
__device__ int   g_tope[NR];
__device__ float g_topw[NR];
__device__ int   g_rows[NR + 128];
__device__ float g_wts[NR + 128];
__device__ float g_h[(size_t)(NR + 128) * DIM];       // hidden activations (padded)
__device__ __half g_wt_hi[2][NE][DIM][DIM];           // W^T [n][k], fp16

// ---------------- init ----------------
__global__ void init_kernel() {
    int t = threadIdx.x;
    if (t < NE) { g_counts[t] = 0; g_cursor[t] = 0; }
}

// ---------------- gate ----------------
__global__ void gate_kernel(const float* __restrict__ x,
                            const float* __restrict__ Wg,
                            const float* __restrict__ bg,
                            float* __restrict__ gate_out) {
    int warp = threadIdx.x >> 5;
    int lane = threadIdx.x & 31;
    int t = blockIdx.x * (blockDim.x >> 5) + warp;
    if (t >= N_TOK) return;

    const float* xr = x + (size_t)t * DIM;
    float acc[NE];
#pragma unroll
    for (int e = 0; e < NE; e++) acc[e] = 0.f;
#pragma unroll
    for (int i = 0; i < DIM / 128; i++) {
        int k0 = i * 128 + lane * 4;
        float4 xv = *(const float4*)(xr + k0);
        float xa[4] = {xv.x, xv.y, xv.z, xv.w};
#pragma unroll
        for (int c = 0; c < 4; c++) {
            const float4 w0 = *(const float4*)(Wg + (size_t)(k0 + c) * NE);
            const float4 w1 = *(const float4*)(Wg + (size_t)(k0 + c) * NE + 4);
            acc[0] += xa[c] * w0.x;  acc[1] += xa[c] * w0.y;
            acc[2] += xa[c] * w0.z;  acc[3] += xa[c] * w0.w;
            acc[4] += xa[c] * w1.x;  acc[5] += xa[c] * w1.y;
            acc[6] += xa[c] * w1.z;  acc[7] += xa[c] * w1.w;
        }
    }
#pragma unroll
    for (int e = 0; e < NE; e++)
#pragma unroll
        for (int o = 16; o > 0; o >>= 1)
            acc[e] += __shfl_xor_sync(0xffffffffu, acc[e], o);

    if (lane == 0) {
        float l[NE], p[NE];
        float m = -1e30f;
#pragma unroll
        for (int e = 0; e < NE; e++) { l[e] = acc[e] + bg[e]; m = fmaxf(m, l[e]); }
        float s = 0.f;
#pragma unroll
        for (int e = 0; e < NE; e++) { p[e] = expf(l[e] - m); s += p[e]; }
        float inv = 1.f / s;
#pragma unroll
        for (int e = 0; e < NE; e++) { p[e] *= inv; gate_out[(size_t)t * NE + e] = p[e]; }

        int e0 = 0; float p0 = p[0];
#pragma unroll
        for (int e = 1; e < NE; e++) if (p[e] > p0) { p0 = p[e]; e0 = e; }
        int e1 = -1; float p1 = -1e30f;
#pragma unroll
        for (int e = 0; e < NE; e++) if (e != e0 && p[e] > p1) { p1 = p[e]; e1 = e; }

        float d  = p1 - p0;
        float ex = expf(d);
        float w0 = 1.f / (1.f + ex);
        float w1 = ex  / (1.f + ex);

        g_tope[2 * t + 0] = e0;  g_topw[2 * t + 0] = w0;
        g_tope[2 * t + 1] = e1;  g_topw[2 * t + 1] = w1;
        atomicAdd(&g_counts[e0], 1);
        atomicAdd(&g_counts[e1], 1);
    }
}

__global__ void scan_kernel() {
    if (threadIdx.x == 0) {
        int s = 0;
        for (int e = 0; e < NE; e++) { g_offsets[e] = s; s += g_counts[e]; }
    }
}

__global__ void route_kernel() {
    int i = blockIdx.x * blockDim.x + threadIdx.x;
    if (i >= NR) return;
    int e = g_tope[i];
    int pos  = atomicAdd(&g_cursor[e], 1);
    int slot = g_offsets[e] + pos;
    g_rows[slot] = i >> 1;
    g_wts[slot]  = g_topw[i];
}

// ---------------- W transpose + fp16 convert ----------------
__global__ void convert_w_kernel(const float* __restrict__ W1,
                                 const float* __restrict__ W2) {
    __shared__ float t[32][33];
    int z = blockIdx.z;               // layer*8 + e
    int layer = z >> 3, e = z & 7;
    int k0 = blockIdx.x * 32, n0 = blockIdx.y * 32;
    int tx = threadIdx.x & 31, ty = threadIdx.x >> 5;

    const float* src = (layer ? W2 : W1) + (size_t)e * DIM * DIM;
#pragma unroll
    for (int i = 0; i < 4; i++) {
        int kk = ty + i * 8;
        t[kk][tx] = src[(size_t)(k0 + kk) * DIM + n0 + tx];
    }
    __syncthreads();
#pragma unroll
    for (int i = 0; i < 4; i++) {
        int nn = ty + i * 8;
        float f = t[tx][nn];
        size_t idx = (size_t)(n0 + nn) * DIM + k0 + tx;
        g_wt_hi[layer][e][0][idx] = __float2half_rn(f);
    }
}

// ---------------- HMMA mma.sync GEMM, 2-term A-split ----------------------
// CTA 128x128, BK=32, 8 warps (4 M x 2 N), warp tile 32x64, m16n8k16.
// D = Ah*Bh + Al*Bh   (A = activations split fp16 hi/lo, B = weights fp16)
#define BK     32
#define SRD    40                     // smem row stride in halfs (conflict-free)
#define TILE_H (128 * SRD)            // 5120 halfs per matrix
#define AHI_O  0
#define ALO_O  TILE_H
#define BHI_O  (2 * TILE_H)
#define STG_H  (3 * TILE_H)           // 15360 halfs = 30KB per stage
#define SMEM_B (2 * STG_H * 2)        // 60KB

#define MMA16816(d, a0, a1, a2, a3, b0, b1) \
    asm volatile("mma.sync.aligned.m16n8k16.row.col.f32.f16.f16.f32 " \
        "{%0,%1,%2,%3}, {%4,%5,%6,%7}, {%8,%9}, {%0,%1,%2,%3};" \
        : "+f"((d)[0]), "+f"((d)[1]), "+f"((d)[2]), "+f"((d)[3]) \
        : "r"(a0), "r"(a1), "r"(a2), "r"(a3), "r"(b0), "r"(b1))

template<int LAYER>
__global__ void __launch_bounds__(256, 1) moe_hmma_kernel(
        const float* __restrict__ Ax,
        const float* __restrict__ bias,
        float* __restrict__ out) {
    const int e = blockIdx.z;
    const int M = g_counts[e];
    const int row0 = blockIdx.y * 128;
    if (row0 >= M) return;
    const int base = g_offsets[e];
    const int bn0  = blockIdx.x * 128;
    const float* bp = bias + (size_t)e * DIM;   // per-expert bias

    extern __shared__ __half sh[];

    const int tid = threadIdx.x;
    const int wid = tid >> 5, lane = tid & 31;
    const int wm = wid >> 1, wn = wid & 1;
    const int g = lane >> 2, q = lane & 3;

    // ---- loader role: thread t handles row r, 16-wide k chunk ks ----
    const int r    = tid >> 1;
    const int ks   = (tid & 1) * 16;
    const int rL   = row0 + r;
    const bool av  = (rL < M);
    const int rr   = av ? rL : 0;
    const float* arow;
    if (LAYER == 1) arow = Ax + (size_t)g_rows[base + rr] * DIM;
    else            arow = g_h + (size_t)(base + rr) * DIM;
    const float4* a4 = (const float4*)arow;
    const __half* bh_row = &g_wt_hi[LAYER - 1][e][bn0 + r][0];

    float acc[16][4];
#pragma unroll
    for (int i = 0; i < 16; i++)
#pragma unroll
        for (int j = 0; j < 4; j++) acc[i][j] = 0.f;

    float4 fa[4];
    uint4  vbh[2];

    auto LOADG = [&](int c) {
        int k0 = c * BK + ks;
        if (av) {
#pragma unroll
            for (int i = 0; i < 4; i++) fa[i] = a4[k0 / 4 + i];
        } else {
#pragma unroll
            for (int i = 0; i < 4; i++) fa[i] = make_float4(0.f, 0.f, 0.f, 0.f);
        }
#pragma unroll
        for (int i = 0; i < 2; i++)
            vbh[i] = *(const uint4*)(bh_row + k0 + i * 8);
    };
    auto STORE = [&](int s) {
        __half* p = sh + s * STG_H;
        float fs[16] = {fa[0].x, fa[0].y, fa[0].z, fa[0].w,
                        fa[1].x, fa[1].y, fa[1].z, fa[1].w,
                        fa[2].x, fa[2].y, fa[2].z, fa[2].w,
                        fa[3].x, fa[3].y, fa[3].z, fa[3].w};
        uint4 hv[2], lv[2];
        __half* hp = (__half*)hv;
        __half* lp = (__half*)lv;
#pragma unroll
        for (int j = 0; j < 16; j++) {
            __half hh = __float2half_rn(fs[j]);
            hp[j] = hh;
            lp[j] = __float2half_rn(fs[j] - __half2float(hh));
        }
        int o = r * SRD + ks;
        *(uint4*)(p + AHI_O + o)     = hv[0];
        *(uint4*)(p + AHI_O + o + 8) = hv[1];
        *(uint4*)(p + ALO_O + o)     = lv[0];
        *(uint4*)(p + ALO_O + o + 8) = lv[1];
        *(uint4*)(p + BHI_O + o)     = vbh[0];
        *(uint4*)(p + BHI_O + o + 8) = vbh[1];
    };

    LOADG(0);
    STORE(0);

    const int NSTG = DIM / BK;   // 32
    for (int c = 0; c < NSTG; c++) {
        __syncthreads();
        const bool more = (c + 1 < NSTG);
        if (more) LOADG(c + 1);

        const __half* p = sh + (c & 1) * STG_H;
#pragma unroll
        for (int k16 = 0; k16 < 2; k16++) {
            u32 af[2][2][4];   // [ms][hi/lo][frag]
#pragma unroll
            for (int ms = 0; ms < 2; ms++) {
                int ab = (wm * 32 + ms * 16 + g) * SRD + k16 * 16 + q * 2;
#pragma unroll
                for (int sp = 0; sp < 2; sp++) {
                    const __half* ap = p + (sp ? ALO_O : AHI_O) + ab;
                    af[ms][sp][0] = *(const u32*)(ap);
                    af[ms][sp][1] = *(const u32*)(ap + 8 * SRD);
                    af[ms][sp][2] = *(const u32*)(ap + 8);
                    af[ms][sp][3] = *(const u32*)(ap + 8 * SRD + 8);
                }
            }
            u32 bf[8][2];
#pragma unroll
            for (int nt = 0; nt < 8; nt++) {
                int bb = (wn * 64 + nt * 8 + g) * SRD + k16 * 16 + q * 2;
                bf[nt][0] = *(const u32*)(p + BHI_O + bb);
                bf[nt][1] = *(const u32*)(p + BHI_O + bb + 8);
            }
            // term-outer ordering: 16 independent accumulator chains per term
#pragma unroll
            for (int sp = 0; sp < 2; sp++)
#pragma unroll
                for (int nt = 0; nt < 8; nt++)
#pragma unroll
                    for (int ms = 0; ms < 2; ms++)
                        MMA16816(acc[ms * 8 + nt],
                                 af[ms][sp][0], af[ms][sp][1], af[ms][sp][2], af[ms][sp][3],
                                 bf[nt][0], bf[nt][1]);
        }
        if (more) STORE((c + 1) & 1);
    }

    // ---- epilogue ----
#pragma unroll
    for (int ms = 0; ms < 2; ms++) {
#pragma unroll
        for (int half = 0; half < 2; half++) {
            int rloc = row0 + wm * 32 + ms * 16 + g + half * 8;
            if (rloc >= M) continue;
            int gslot = base + rloc;
            if (LAYER == 1) {
                float* hrow = g_h + (size_t)gslot * DIM;
#pragma unroll
                for (int nt = 0; nt < 8; nt++) {
                    int col = bn0 + wn * 64 + nt * 8 + q * 2;
                    float b0 = bp[col], b1 = bp[col + 1];
                    float v0 = fmaxf(acc[ms * 8 + nt][half * 2 + 0] + b0, 0.f);
                    float v1 = fmaxf(acc[ms * 8 + nt][half * 2 + 1] + b1, 0.f);
                    *(float2*)(hrow + col) = make_float2(v0, v1);
                }
            } else {
                int tok = g_rows[gslot];
                float cw = g_wts[gslot];
                float* yr = out + (size_t)tok * DIM;
#pragma unroll
                for (int nt = 0; nt < 8; nt++) {
                    int col = bn0 + wn * 64 + nt * 8 + q * 2;
                    float b0 = bp[col], b1 = bp[col + 1];
                    atomicAdd(yr + col + 0, cw * (acc[ms * 8 + nt][half * 2 + 0] + b0));
                    atomicAdd(yr + col + 1, cw * (acc[ms * 8 + nt][half * 2 + 1] + b1));
                }
            }
        }
    }
}

// ---------------- launch ----------------
extern "C" void kernel_launch(void* const* d_in, const int* in_sizes, int n_in,
                              void* d_out, int out_size) {
    const float* x  = (const float*)d_in[0];
    const float* Wg = (const float*)d_in[1];
    const float* bg = (const float*)d_in[2];
    const float* W1 = (const float*)d_in[3];
    const float* b1 = (const float*)d_in[4];
    const float* W2 = (const float*)d_in[5];
    const float* b2 = (const float*)d_in[6];

    float* y        = (float*)d_out;
    float* gate_out = (float*)d_out + (size_t)N_TOK * DIM;

    static int attr_done = 0;
    if (!attr_done) {
        cudaFuncSetAttribute(moe_hmma_kernel<1>,
            cudaFuncAttributeMaxDynamicSharedMemorySize, SMEM_B);
        cudaFuncSetAttribute(moe_hmma_kernel<2>,
            cudaFuncAttributeMaxDynamicSharedMemorySize, SMEM_B);
        attr_done = 1;
    }

    cudaMemsetAsync(d_out, 0, (size_t)N_TOK * DIM * sizeof(float), 0);

    init_kernel<<<1, 32>>>();
    convert_w_kernel<<<dim3(DIM / 32, DIM / 32, 16), 256>>>(W1, W2);
    gate_kernel<<<N_TOK / 8, 256>>>(x, Wg, bg, gate_out);
    scan_kernel<<<1, 1>>>();
    route_kernel<<<NR / 256, 256>>>();

    dim3 grid(DIM / 128, NR / 128, NE);
    moe_hmma_kernel<1><<<grid, 256, SMEM_B>>>(x, b1, nullptr);
    moe_hmma_kernel<2><<<grid, 256, SMEM_B>>>(nullptr, b2, y);
}

// round 7
// speedup vs baseline: 3.2803x; 1.3656x over previous
#include <cuda_runtime.h>
#include <cuda_fp16.h>
#include <math.h>
#include <stdint.h>

#define N_TOK 8192
#define DIM   1024
#define NE    8
#define NR    (N_TOK * 2)

typedef uint32_t u32;

// ---------------- scratch (device globals; no allocation) ----------------
__device__ int   g_counts[NE];
__device__ int   g_offsets[NE];
__device__ int   g_cursor[NE];
__device__ int   g_tope[NR];
__device__ float g_topw[NR];
__device__ int   g_rows[NR + 128];
__device__ float g_wts[NR + 128];
__device__ float g_h[(size_t)(NR + 128) * DIM];       // hidden activations (padded)
__device__ __half g_wt[2][NE][DIM][DIM];              // W^T [n][k], fp16

// ---------------- init ----------------
__global__ void init_kernel() {
    int t = threadIdx.x;
    if (t < NE) { g_counts[t] = 0; g_cursor[t] = 0; }
}

// ---------------- gate ----------------
__global__ void gate_kernel(const float* __restrict__ x,
                            const float* __restrict__ Wg,
                            const float* __restrict__ bg,
                            float* __restrict__ gate_out) {
    int warp = threadIdx.x >> 5;
    int lane = threadIdx.x & 31;
    int t = blockIdx.x * (blockDim.x >> 5) + warp;
    if (t >= N_TOK) return;

    const float* xr = x + (size_t)t * DIM;
    float acc[NE];
#pragma unroll
    for (int e = 0; e < NE; e++) acc[e] = 0.f;
#pragma unroll
    for (int i = 0; i < DIM / 128; i++) {
        int k0 = i * 128 + lane * 4;
        float4 xv = *(const float4*)(xr + k0);
        float xa[4] = {xv.x, xv.y, xv.z, xv.w};
#pragma unroll
        for (int c = 0; c < 4; c++) {
            const float4 w0 = *(const float4*)(Wg + (size_t)(k0 + c) * NE);
            const float4 w1 = *(const float4*)(Wg + (size_t)(k0 + c) * NE + 4);
            acc[0] += xa[c] * w0.x;  acc[1] += xa[c] * w0.y;
            acc[2] += xa[c] * w0.z;  acc[3] += xa[c] * w0.w;
            acc[4] += xa[c] * w1.x;  acc[5] += xa[c] * w1.y;
            acc[6] += xa[c] * w1.z;  acc[7] += xa[c] * w1.w;
        }
    }
#pragma unroll
    for (int e = 0; e < NE; e++)
#pragma unroll
        for (int o = 16; o > 0; o >>= 1)
            acc[e] += __shfl_xor_sync(0xffffffffu, acc[e], o);

    if (lane == 0) {
        float l[NE], p[NE];
        float m = -1e30f;
#pragma unroll
        for (int e = 0; e < NE; e++) { l[e] = acc[e] + bg[e]; m = fmaxf(m, l[e]); }
        float s = 0.f;
#pragma unroll
        for (int e = 0; e < NE; e++) { p[e] = expf(l[e] - m); s += p[e]; }
        float inv = 1.f / s;
#pragma unroll
        for (int e = 0; e < NE; e++) { p[e] *= inv; gate_out[(size_t)t * NE + e] = p[e]; }

        int e0 = 0; float p0 = p[0];
#pragma unroll
        for (int e = 1; e < NE; e++) if (p[e] > p0) { p0 = p[e]; e0 = e; }
        int e1 = -1; float p1 = -1e30f;
#pragma unroll
        for (int e = 0; e < NE; e++) if (e != e0 && p[e] > p1) { p1 = p[e]; e1 = e; }

        float d  = p1 - p0;
        float ex = expf(d);
        float w0 = 1.f / (1.f + ex);
        float w1 = ex  / (1.f + ex);

        g_tope[2 * t + 0] = e0;  g_topw[2 * t + 0] = w0;
        g_tope[2 * t + 1] = e1;  g_topw[2 * t + 1] = w1;
        atomicAdd(&g_counts[e0], 1);
        atomicAdd(&g_counts[e1], 1);
    }
}

__global__ void scan_kernel() {
    if (threadIdx.x == 0) {
        int s = 0;
        for (int e = 0; e < NE; e++) { g_offsets[e] = s; s += g_counts[e]; }
    }
}

__global__ void route_kernel() {
    int i = blockIdx.x * blockDim.x + threadIdx.x;
    if (i >= NR) return;
    int e = g_tope[i];
    int pos  = atomicAdd(&g_cursor[e], 1);
    int slot = g_offsets[e] + pos;
    g_rows[slot] = i >> 1;
    g_wts[slot]  = g_topw[i];
}

// ---------------- W transpose + fp16 convert ----------------
__global__ void convert_w_kernel(const float* __restrict__ W1,
                                 const float* __restrict__ W2) {
    __shared__ float t[32][33];
    int z = blockIdx.z;               // layer*8 + e
    int layer = z >> 3, e = z & 7;
    int k0 = blockIdx.x * 32, n0 = blockIdx.y * 32;
    int tx = threadIdx.x & 31, ty = threadIdx.x >> 5;

    const float* src = (layer ? W2 : W1) + (size_t)e * DIM * DIM;
#pragma unroll
    for (int i = 0; i < 4; i++) {
        int kk = ty + i * 8;
        t[kk][tx] = src[(size_t)(k0 + kk) * DIM + n0 + tx];
    }
    __syncthreads();
#pragma unroll
    for (int i = 0; i < 4; i++) {
        int nn = ty + i * 8;
        float f = t[tx][nn];
        size_t idx = (size_t)(n0 + nn) * DIM + k0 + tx;
        g_wt[layer][e][0][idx] = __float2half_rn(f);
    }
}

// ---------------- HMMA mma.sync GEMM, single fp16 -------------------------
// CTA 128x128, BK=32, 8 warps (4 M x 2 N), warp tile 32x64, m16n8k16.
#define BK     32
#define SRD    40                     // smem row stride in halfs (conflict-free)
#define TILE_H (128 * SRD)            // 5120 halfs per matrix
#define A_O    0
#define B_O    TILE_H
#define STG_H  (2 * TILE_H)           // 10240 halfs = 20KB per stage
#define SMEM_B (2 * STG_H * 2)        // 40KB

#define MMA16816(d, a0, a1, a2, a3, b0, b1) \
    asm volatile("mma.sync.aligned.m16n8k16.row.col.f32.f16.f16.f32 " \
        "{%0,%1,%2,%3}, {%4,%5,%6,%7}, {%8,%9}, {%0,%1,%2,%3};" \
        : "+f"((d)[0]), "+f"((d)[1]), "+f"((d)[2]), "+f"((d)[3]) \
        : "r"(a0), "r"(a1), "r"(a2), "r"(a3), "r"(b0), "r"(b1))

template<int LAYER>
__global__ void __launch_bounds__(256, 2) moe_hmma_kernel(
        const float* __restrict__ Ax,
        const float* __restrict__ bias,
        float* __restrict__ out) {
    const int e = blockIdx.z;
    const int M = g_counts[e];
    const int row0 = blockIdx.y * 128;
    if (row0 >= M) return;
    const int base = g_offsets[e];
    const int bn0  = blockIdx.x * 128;
    const float* bp = bias + (size_t)e * DIM;   // per-expert bias

    extern __shared__ __half sh[];

    const int tid = threadIdx.x;
    const int wid = tid >> 5, lane = tid & 31;
    const int wm = wid >> 1, wn = wid & 1;
    const int g = lane >> 2, q = lane & 3;

    // ---- loader role: thread t handles row r, 16-wide k chunk ks ----
    const int r    = tid >> 1;
    const int ks   = (tid & 1) * 16;
    const int rL   = row0 + r;
    const bool av  = (rL < M);
    const int rr   = av ? rL : 0;
    const float* arow;
    if (LAYER == 1) arow = Ax + (size_t)g_rows[base + rr] * DIM;
    else            arow = g_h + (size_t)(base + rr) * DIM;
    const float4* a4 = (const float4*)arow;
    const __half* b_row = &g_wt[LAYER - 1][e][bn0 + r][0];

    float acc[16][4];
#pragma unroll
    for (int i = 0; i < 16; i++)
#pragma unroll
        for (int j = 0; j < 4; j++) acc[i][j] = 0.f;

    float4 fa[4];
    uint4  vb[2];

    auto LOADG = [&](int c) {
        int k0 = c * BK + ks;
        if (av) {
#pragma unroll
            for (int i = 0; i < 4; i++) fa[i] = a4[k0 / 4 + i];
        } else {
#pragma unroll
            for (int i = 0; i < 4; i++) fa[i] = make_float4(0.f, 0.f, 0.f, 0.f);
        }
#pragma unroll
        for (int i = 0; i < 2; i++)
            vb[i] = *(const uint4*)(b_row + k0 + i * 8);
    };
    auto STORE = [&](int s) {
        __half* p = sh + s * STG_H;
        float fs[16] = {fa[0].x, fa[0].y, fa[0].z, fa[0].w,
                        fa[1].x, fa[1].y, fa[1].z, fa[1].w,
                        fa[2].x, fa[2].y, fa[2].z, fa[2].w,
                        fa[3].x, fa[3].y, fa[3].z, fa[3].w};
        uint4 hv[2];
        __half* hp = (__half*)hv;
#pragma unroll
        for (int j = 0; j < 16; j++) hp[j] = __float2half_rn(fs[j]);
        int o = r * SRD + ks;
        *(uint4*)(p + A_O + o)     = hv[0];
        *(uint4*)(p + A_O + o + 8) = hv[1];
        *(uint4*)(p + B_O + o)     = vb[0];
        *(uint4*)(p + B_O + o + 8) = vb[1];
    };

    LOADG(0);
    STORE(0);

    const int NSTG = DIM / BK;   // 32
    for (int c = 0; c < NSTG; c++) {
        __syncthreads();
        const bool more = (c + 1 < NSTG);
        if (more) LOADG(c + 1);

        const __half* p = sh + (c & 1) * STG_H;
#pragma unroll
        for (int k16 = 0; k16 < 2; k16++) {
            u32 af[2][4];
#pragma unroll
            for (int ms = 0; ms < 2; ms++) {
                int ab = (wm * 32 + ms * 16 + g) * SRD + k16 * 16 + q * 2;
                const __half* ap = p + A_O + ab;
                af[ms][0] = *(const u32*)(ap);
                af[ms][1] = *(const u32*)(ap + 8 * SRD);
                af[ms][2] = *(const u32*)(ap + 8);
                af[ms][3] = *(const u32*)(ap + 8 * SRD + 8);
            }
            u32 bf[8][2];
#pragma unroll
            for (int nt = 0; nt < 8; nt++) {
                int bb = (wn * 64 + nt * 8 + g) * SRD + k16 * 16 + q * 2;
                bf[nt][0] = *(const u32*)(p + B_O + bb);
                bf[nt][1] = *(const u32*)(p + B_O + bb + 8);
            }
#pragma unroll
            for (int nt = 0; nt < 8; nt++)
#pragma unroll
                for (int ms = 0; ms < 2; ms++)
                    MMA16816(acc[ms * 8 + nt],
                             af[ms][0], af[ms][1], af[ms][2], af[ms][3],
                             bf[nt][0], bf[nt][1]);
        }
        if (more) STORE((c + 1) & 1);
    }

    // ---- epilogue ----
#pragma unroll
    for (int ms = 0; ms < 2; ms++) {
#pragma unroll
        for (int half = 0; half < 2; half++) {
            int rloc = row0 + wm * 32 + ms * 16 + g + half * 8;
            if (rloc >= M) continue;
            int gslot = base + rloc;
            if (LAYER == 1) {
                float* hrow = g_h + (size_t)gslot * DIM;
#pragma unroll
                for (int nt = 0; nt < 8; nt++) {
                    int col = bn0 + wn * 64 + nt * 8 + q * 2;
                    float b0 = bp[col], b1 = bp[col + 1];
                    float v0 = fmaxf(acc[ms * 8 + nt][half * 2 + 0] + b0, 0.f);
                    float v1 = fmaxf(acc[ms * 8 + nt][half * 2 + 1] + b1, 0.f);
                    *(float2*)(hrow + col) = make_float2(v0, v1);
                }
            } else {
                int tok = g_rows[gslot];
                float cw = g_wts[gslot];
                float* yr = out + (size_t)tok * DIM;
#pragma unroll
                for (int nt = 0; nt < 8; nt++) {
                    int col = bn0 + wn * 64 + nt * 8 + q * 2;
                    float b0 = bp[col], b1 = bp[col + 1];
                    atomicAdd(yr + col + 0, cw * (acc[ms * 8 + nt][half * 2 + 0] + b0));
                    atomicAdd(yr + col + 1, cw * (acc[ms * 8 + nt][half * 2 + 1] + b1));
                }
            }
        }
    }
}

// ---------------- launch ----------------
extern "C" void kernel_launch(void* const* d_in, const int* in_sizes, int n_in,
                              void* d_out, int out_size) {
    const float* x  = (const float*)d_in[0];
    const float* Wg = (const float*)d_in[1];
    const float* bg = (const float*)d_in[2];
    const float* W1 = (const float*)d_in[3];
    const float* b1 = (const float*)d_in[4];
    const float* W2 = (const float*)d_in[5];
    const float* b2 = (const float*)d_in[6];

    float* y        = (float*)d_out;
    float* gate_out = (float*)d_out + (size_t)N_TOK * DIM;

    static int attr_done = 0;
    if (!attr_done) {
        cudaFuncSetAttribute(moe_hmma_kernel<1>,
            cudaFuncAttributeMaxDynamicSharedMemorySize, SMEM_B);
        cudaFuncSetAttribute(moe_hmma_kernel<2>,
            cudaFuncAttributeMaxDynamicSharedMemorySize, SMEM_B);
        attr_done = 1;
    }

    cudaMemsetAsync(d_out, 0, (size_t)N_TOK * DIM * sizeof(float), 0);

    init_kernel<<<1, 32>>>();
    convert_w_kernel<<<dim3(DIM / 32, DIM / 32, 16), 256>>>(W1, W2);
    gate_kernel<<<N_TOK / 8, 256>>>(x, Wg, bg, gate_out);
    scan_kernel<<<1, 1>>>();
    route_kernel<<<NR / 256, 256>>>();

    dim3 grid(DIM / 128, NR / 128, NE);
    moe_hmma_kernel<1><<<grid, 256, SMEM_B>>>(x, b1, nullptr);
    moe_hmma_kernel<2><<<grid, 256, SMEM_B>>>(nullptr, b2, y);
}

// round 8
// speedup vs baseline: 4.1863x; 1.2762x over previous
#include <cuda_runtime.h>
#include <cuda_fp16.h>
#include <math.h>
#include <stdint.h>

#define N_TOK 8192
#define DIM   1024
#define NE    8
#define NR    (N_TOK * 2)

typedef uint32_t u32;

// ---------------- scratch (device globals; no allocation) ----------------
__device__ int    g_counts[NE];
__device__ int    g_offsets[NE];
__device__ int    g_cursor[NE];
__device__ int    g_tope[NR];
__device__ float  g_topw[NR];
__device__ int    g_rows[NR + 128];
__device__ float  g_wts[NR + 128];
__device__ __half g_xh[(size_t)N_TOK * DIM];           // x in fp16
__device__ __half g_h[(size_t)(NR + 128) * DIM];       // hidden acts, fp16
__device__ __half g_wt[2][NE][DIM][DIM];               // W^T [n][k], fp16

// ---------------- init ----------------
__global__ void init_kernel() {
    int t = threadIdx.x;
    if (t < NE) { g_counts[t] = 0; g_cursor[t] = 0; }
}

// ---------------- gate (also emits x_fp16) ----------------
__global__ void gate_kernel(const float* __restrict__ x,
                            const float* __restrict__ Wg,
                            const float* __restrict__ bg,
                            float* __restrict__ gate_out) {
    int warp = threadIdx.x >> 5;
    int lane = threadIdx.x & 31;
    int t = blockIdx.x * (blockDim.x >> 5) + warp;
    if (t >= N_TOK) return;

    const float* xr = x + (size_t)t * DIM;
    float acc[NE];
#pragma unroll
    for (int e = 0; e < NE; e++) acc[e] = 0.f;
#pragma unroll
    for (int i = 0; i < DIM / 128; i++) {
        int k0 = i * 128 + lane * 4;
        float4 xv = *(const float4*)(xr + k0);
        // emit fp16 copy of x (coalesced 8B per lane)
        __half2 h01 = __halves2half2(__float2half_rn(xv.x), __float2half_rn(xv.y));
        __half2 h23 = __halves2half2(__float2half_rn(xv.z), __float2half_rn(xv.w));
        *(__half2*)(&g_xh[(size_t)t * DIM + k0])     = h01;
        *(__half2*)(&g_xh[(size_t)t * DIM + k0 + 2]) = h23;

        float xa[4] = {xv.x, xv.y, xv.z, xv.w};
#pragma unroll
        for (int c = 0; c < 4; c++) {
            const float4 w0 = *(const float4*)(Wg + (size_t)(k0 + c) * NE);
            const float4 w1 = *(const float4*)(Wg + (size_t)(k0 + c) * NE + 4);
            acc[0] += xa[c] * w0.x;  acc[1] += xa[c] * w0.y;
            acc[2] += xa[c] * w0.z;  acc[3] += xa[c] * w0.w;
            acc[4] += xa[c] * w1.x;  acc[5] += xa[c] * w1.y;
            acc[6] += xa[c] * w1.z;  acc[7] += xa[c] * w1.w;
        }
    }
#pragma unroll
    for (int e = 0; e < NE; e++)
#pragma unroll
        for (int o = 16; o > 0; o >>= 1)
            acc[e] += __shfl_xor_sync(0xffffffffu, acc[e], o);

    if (lane == 0) {
        float l[NE], p[NE];
        float m = -1e30f;
#pragma unroll
        for (int e = 0; e < NE; e++) { l[e] = acc[e] + bg[e]; m = fmaxf(m, l[e]); }
        float s = 0.f;
#pragma unroll
        for (int e = 0; e < NE; e++) { p[e] = expf(l[e] - m); s += p[e]; }
        float inv = 1.f / s;
#pragma unroll
        for (int e = 0; e < NE; e++) { p[e] *= inv; gate_out[(size_t)t * NE + e] = p[e]; }

        int e0 = 0; float p0 = p[0];
#pragma unroll
        for (int e = 1; e < NE; e++) if (p[e] > p0) { p0 = p[e]; e0 = e; }
        int e1 = -1; float p1 = -1e30f;
#pragma unroll
        for (int e = 0; e < NE; e++) if (e != e0 && p[e] > p1) { p1 = p[e]; e1 = e; }

        float d  = p1 - p0;
        float ex = expf(d);
        float w0 = 1.f / (1.f + ex);
        float w1 = ex  / (1.f + ex);

        g_tope[2 * t + 0] = e0;  g_topw[2 * t + 0] = w0;
        g_tope[2 * t + 1] = e1;  g_topw[2 * t + 1] = w1;
        atomicAdd(&g_counts[e0], 1);
        atomicAdd(&g_counts[e1], 1);
    }
}

__global__ void scan_kernel() {
    if (threadIdx.x == 0) {
        int s = 0;
        for (int e = 0; e < NE; e++) { g_offsets[e] = s; s += g_counts[e]; }
    }
}

__global__ void route_kernel() {
    int i = blockIdx.x * blockDim.x + threadIdx.x;
    if (i >= NR) return;
    int e = g_tope[i];
    int pos  = atomicAdd(&g_cursor[e], 1);
    int slot = g_offsets[e] + pos;
    g_rows[slot] = i >> 1;
    g_wts[slot]  = g_topw[i];
}

// ---------------- W transpose + fp16 convert ----------------
__global__ void convert_w_kernel(const float* __restrict__ W1,
                                 const float* __restrict__ W2) {
    __shared__ float t[32][33];
    int z = blockIdx.z;               // layer*8 + e
    int layer = z >> 3, e = z & 7;
    int k0 = blockIdx.x * 32, n0 = blockIdx.y * 32;
    int tx = threadIdx.x & 31, ty = threadIdx.x >> 5;

    const float* src = (layer ? W2 : W1) + (size_t)e * DIM * DIM;
#pragma unroll
    for (int i = 0; i < 4; i++) {
        int kk = ty + i * 8;
        t[kk][tx] = src[(size_t)(k0 + kk) * DIM + n0 + tx];
    }
    __syncthreads();
#pragma unroll
    for (int i = 0; i < 4; i++) {
        int nn = ty + i * 8;
        float f = t[tx][nn];
        size_t idx = (size_t)(n0 + nn) * DIM + k0 + tx;
        g_wt[layer][e][0][idx] = __float2half_rn(f);
    }
}

// ---------------- HMMA GEMM: cp.async 4-stage pipeline --------------------
// CTA 128x128, BK=32, 8 warps (4 M x 2 N), warp tile 32x64, m16n8k16.
#define BK      32
#define SRD     40                    // smem row stride in halfs (conflict-free)
#define TILE_H  (128 * SRD)           // 5120 halfs per matrix
#define A_O     0
#define B_O     TILE_H
#define STG_H   (2 * TILE_H)          // 10240 halfs = 20KB per stage
#define STAGES  4
#define SMEM_B  (STAGES * STG_H * 2)  // 80KB

#define CP_ASYNC16(dst, src) \
    asm volatile("cp.async.cg.shared.global [%0], [%1], 16;" \
        :: "r"(dst), "l"(src) : "memory")
#define CP_COMMIT() asm volatile("cp.async.commit_group;" ::: "memory")
#define CP_WAIT2()  asm volatile("cp.async.wait_group 2;"  ::: "memory")

#define MMA16816(d, a0, a1, a2, a3, b0, b1) \
    asm volatile("mma.sync.aligned.m16n8k16.row.col.f32.f16.f16.f32 " \
        "{%0,%1,%2,%3}, {%4,%5,%6,%7}, {%8,%9}, {%0,%1,%2,%3};" \
        : "+f"((d)[0]), "+f"((d)[1]), "+f"((d)[2]), "+f"((d)[3]) \
        : "r"(a0), "r"(a1), "r"(a2), "r"(a3), "r"(b0), "r"(b1))

__device__ __forceinline__ u32 smem_u32(const void* p) {
    u32 a;
    asm("{ .reg .u64 t; cvta.to.shared.u64 t, %1; cvt.u32.u64 %0, t; }" : "=r"(a) : "l"(p));
    return a;
}

template<int LAYER>
__global__ void __launch_bounds__(256, 2) moe_hmma_kernel(
        const float* __restrict__ bias,
        float* __restrict__ out) {
    const int e = blockIdx.z;
    const int M = g_counts[e];
    const int row0 = blockIdx.y * 128;
    if (row0 >= M) return;
    const int base = g_offsets[e];
    const int bn0  = blockIdx.x * 128;
    const float* bp = bias + (size_t)e * DIM;

    extern __shared__ __half sh[];
    const u32 sb = smem_u32(sh);

    const int tid = threadIdx.x;
    const int wid = tid >> 5, lane = tid & 31;
    const int wm = wid >> 1, wn = wid & 1;
    const int g = lane >> 2, q = lane & 3;

    // ---- loader role: thread t -> row r, 16-half chunk ks ----
    const int r   = tid >> 1;
    const int ks  = (tid & 1) * 16;
    const int rL  = row0 + r;
    const int rr  = (rL < M) ? rL : 0;
    const __half* arow;
    if (LAYER == 1) arow = g_xh + (size_t)g_rows[base + rr] * DIM;
    else            arow = g_h + (size_t)(base + rr) * DIM;
    const __half* brow = &g_wt[LAYER - 1][e][bn0 + r][0];

    const u32 dA = sb + (u32)(A_O + r * SRD + ks) * 2;
    const u32 dB = sb + (u32)(B_O + r * SRD + ks) * 2;

    float acc[16][4];
#pragma unroll
    for (int i = 0; i < 16; i++)
#pragma unroll
        for (int j = 0; j < 4; j++) acc[i][j] = 0.f;

    auto ISSUE = [&](int c) {
        const u32 so = (u32)((c & (STAGES - 1)) * STG_H) * 2;
        const int k0 = c * BK + ks;
        CP_ASYNC16(dA + so,      arow + k0);
        CP_ASYNC16(dA + so + 16, arow + k0 + 8);
        CP_ASYNC16(dB + so,      brow + k0);
        CP_ASYNC16(dB + so + 16, brow + k0 + 8);
    };

    // prologue: stages 0..2
#pragma unroll
    for (int s = 0; s < STAGES - 1; s++) { ISSUE(s); CP_COMMIT(); }

    const int NSTG = DIM / BK;   // 32
    for (int c = 0; c < NSTG; c++) {
        CP_WAIT2();
        __syncthreads();
        if (c + STAGES - 1 < NSTG) ISSUE(c + STAGES - 1);
        CP_COMMIT();

        const __half* p = sh + (c & (STAGES - 1)) * STG_H;
#pragma unroll
        for (int k16 = 0; k16 < 2; k16++) {
            u32 af[2][4];
#pragma unroll
            for (int ms = 0; ms < 2; ms++) {
                int ab = (wm * 32 + ms * 16 + g) * SRD + k16 * 16 + q * 2;
                const __half* ap = p + A_O + ab;
                af[ms][0] = *(const u32*)(ap);
                af[ms][1] = *(const u32*)(ap + 8 * SRD);
                af[ms][2] = *(const u32*)(ap + 8);
                af[ms][3] = *(const u32*)(ap + 8 * SRD + 8);
            }
            u32 bf[8][2];
#pragma unroll
            for (int nt = 0; nt < 8; nt++) {
                int bb = (wn * 64 + nt * 8 + g) * SRD + k16 * 16 + q * 2;
                bf[nt][0] = *(const u32*)(p + B_O + bb);
                bf[nt][1] = *(const u32*)(p + B_O + bb + 8);
            }
#pragma unroll
            for (int nt = 0; nt < 8; nt++)
#pragma unroll
                for (int ms = 0; ms < 2; ms++)
                    MMA16816(acc[ms * 8 + nt],
                             af[ms][0], af[ms][1], af[ms][2], af[ms][3],
                             bf[nt][0], bf[nt][1]);
        }
    }

    // ---- epilogue ----
#pragma unroll
    for (int ms = 0; ms < 2; ms++) {
#pragma unroll
        for (int half = 0; half < 2; half++) {
            int rloc = row0 + wm * 32 + ms * 16 + g + half * 8;
            if (rloc >= M) continue;
            int gslot = base + rloc;
            if (LAYER == 1) {
                __half* hrow = g_h + (size_t)gslot * DIM;
#pragma unroll
                for (int nt = 0; nt < 8; nt++) {
                    int col = bn0 + wn * 64 + nt * 8 + q * 2;
                    float b0 = bp[col], b1 = bp[col + 1];
                    float v0 = fmaxf(acc[ms * 8 + nt][half * 2 + 0] + b0, 0.f);
                    float v1 = fmaxf(acc[ms * 8 + nt][half * 2 + 1] + b1, 0.f);
                    *(__half2*)(hrow + col) =
                        __halves2half2(__float2half_rn(v0), __float2half_rn(v1));
                }
            } else {
                int tok = g_rows[gslot];
                float cw = g_wts[gslot];
                float* yr = out + (size_t)tok * DIM;
#pragma unroll
                for (int nt = 0; nt < 8; nt++) {
                    int col = bn0 + wn * 64 + nt * 8 + q * 2;
                    float b0 = bp[col], b1 = bp[col + 1];
                    atomicAdd(yr + col + 0, cw * (acc[ms * 8 + nt][half * 2 + 0] + b0));
                    atomicAdd(yr + col + 1, cw * (acc[ms * 8 + nt][half * 2 + 1] + b1));
                }
            }
        }
    }
}

// ---------------- launch ----------------
extern "C" void kernel_launch(void* const* d_in, const int* in_sizes, int n_in,
                              void* d_out, int out_size) {
    const float* x  = (const float*)d_in[0];
    const float* Wg = (const float*)d_in[1];
    const float* bg = (const float*)d_in[2];
    const float* W1 = (const float*)d_in[3];
    const float* b1 = (const float*)d_in[4];
    const float* W2 = (const float*)d_in[5];
    const float* b2 = (const float*)d_in[6];

    float* y        = (float*)d_out;
    float* gate_out = (float*)d_out + (size_t)N_TOK * DIM;

    static int attr_done = 0;
    if (!attr_done) {
        cudaFuncSetAttribute(moe_hmma_kernel<1>,
            cudaFuncAttributeMaxDynamicSharedMemorySize, SMEM_B);
        cudaFuncSetAttribute(moe_hmma_kernel<2>,
            cudaFuncAttributeMaxDynamicSharedMemorySize, SMEM_B);
        attr_done = 1;
    }

    cudaMemsetAsync(d_out, 0, (size_t)N_TOK * DIM * sizeof(float), 0);

    init_kernel<<<1, 32>>>();
    convert_w_kernel<<<dim3(DIM / 32, DIM / 32, 16), 256>>>(W1, W2);
    gate_kernel<<<N_TOK / 8, 256>>>(x, Wg, bg, gate_out);
    scan_kernel<<<1, 1>>>();
    route_kernel<<<NR / 256, 256>>>();

    dim3 grid(DIM / 128, NR / 128, NE);
    moe_hmma_kernel<1><<<grid, 256, SMEM_B>>>(b1, nullptr);
    moe_hmma_kernel<2><<<grid, 256, SMEM_B>>>(b2, y);
}